// round 8
// baseline (speedup 1.0000x reference)
#include <cuda_runtime.h>
#include <cuda_fp16.h>
#include <mma.h>

using namespace nvcuda;

#define NMAX 100000
#define EMAX 1600000
#define TOTMAX (EMAX + NMAX)
#define PAD_ROWS 128

struct alignas(8) CN { int c; float nw; };

// ---------------- scratch (static device globals; no allocation) -------------
__device__ int    g_deg[NMAX];           // zero-init; restored to 0 by fill
__device__ float  g_dinv[NMAX];
__device__ int    g_rowptr[NMAX + 1];
__device__ int    g_bsum[128];
__device__ CN     g_cn[TOTMAX];
__device__ __half g_bufA[(size_t)(NMAX + PAD_ROWS) * 128];
__device__ __half g_bufB[(size_t)(NMAX + PAD_ROWS) * 128];
__device__ __half g_bufC[(size_t)(NMAX + PAD_ROWS) * 128];
__device__ __half g_w0h[128 * 128];
__device__ __half g_w1h[128 * 128];
__device__ __half g_w2h[128 * 48];   // W2 padded 40 -> 48 cols (zeros)

// ---------------- preprocessing ----------------------------------------------

__global__ void degree_kernel(const int* __restrict__ ei, int e) {
    int i = blockIdx.x * blockDim.x + threadIdx.x;
    if (i < e) atomicAdd(&g_deg[ei[e + i]], 1);   // dst = ei[E + i]
}

__global__ void scan1_kernel(int n) {
    __shared__ int s[1024];
    int t = threadIdx.x;
    int i = blockIdx.x * 1024 + t;
    int v = 0;
    if (i < n) {
        v = g_deg[i] + 1;                  // +1 self-loop
        g_dinv[i] = rsqrtf((float)v);
    }
    s[t] = v;
    __syncthreads();
    for (int off = 1; off < 1024; off <<= 1) {
        int x = (t >= off) ? s[t - off] : 0;
        __syncthreads();
        s[t] += x;
        __syncthreads();
    }
    if (i < n) g_rowptr[i + 1] = s[t];
    if (t == 1023) g_bsum[blockIdx.x] = s[1023];
}

__global__ void scan2_kernel(int nb) {
    __shared__ int ws[4];
    int t = threadIdx.x;              // 128 threads
    int lane = t & 31, w = t >> 5;
    int orig = (t < nb) ? g_bsum[t] : 0;
    int v = orig;
    for (int off = 1; off < 32; off <<= 1) {
        int x = __shfl_up_sync(0xffffffffu, v, off);
        if (lane >= off) v += x;
    }
    if (lane == 31) ws[w] = v;
    __syncthreads();
    int add = 0;
    for (int i = 0; i < w; i++) add += ws[i];
    v += add;
    if (t < nb) g_bsum[t] = v - orig;  // exclusive
}

__global__ void scan3_kernel(int n) {
    int i = blockIdx.x * blockDim.x + threadIdx.x;
    if (i < n) g_rowptr[i + 1] += g_bsum[i >> 10];
    if (i == 0) g_rowptr[0] = 0;
}

// atomicSub consumes the degree counts, leaving g_deg back at all-zero.
__global__ void fill_kernel(const int* __restrict__ ei, int e, int n) {
    int i = blockIdx.x * blockDim.x + threadIdx.x;
    if (i < e) {
        int s = ei[i], d = ei[e + i];
        int pos = atomicSub(&g_deg[d], 1) - 1;
        int idx = g_rowptr[d] + pos;
        CN cn; cn.c = s; cn.nw = g_dinv[s] * g_dinv[d];
        g_cn[idx] = cn;
    } else if (i < e + n) {
        int d = i - e;
        int idx = g_rowptr[d + 1] - 1;
        float dv = g_dinv[d];
        CN cn; cn.c = d; cn.nw = dv * dv;
        g_cn[idx] = cn;
    }
}

__global__ void convert_w_kernel(const float* __restrict__ W0, const float* __restrict__ W1,
                                 const float* __restrict__ W2) {
    int i = blockIdx.x * blockDim.x + threadIdx.x;   // 0 .. 38911
    if (i < 16384) {
        g_w0h[i] = __float2half(W0[i]);
    } else if (i < 32768) {
        g_w1h[i - 16384] = __float2half(W1[i - 16384]);
    } else if (i < 32768 + 128 * 48) {
        int j = i - 32768;
        int r = j / 48, c = j % 48;
        g_w2h[j] = (c < 40) ? __float2half(W2[r * 40 + c]) : __half(0.f);
    }
}

// ---------------- smem-staged tensor-core GEMMs -------------------------------

// C[n,128](half) = A[n,128] @ W[128,128](half). BM=128, BK=64 (2 chunks).
template <bool F32IN>
__global__ __launch_bounds__(256) void gemm128_smem(const void* __restrict__ Ain,
                                                    const __half* __restrict__ W,
                                                    __half2* __restrict__ C, int n) {
    __shared__ __half As[128][72];
    __shared__ __half Ws[64][136];
    __shared__ float  cs[8][16][20];

    const int tid = threadIdx.x;
    const int w = tid >> 5, lane = tid & 31;
    const int wm = w >> 2, wn = w & 3;
    const int row0 = blockIdx.x * 128;

    wmma::fragment<wmma::accumulator, 16, 16, 16, float> acc[4][2];
#pragma unroll
    for (int i = 0; i < 4; i++)
#pragma unroll
        for (int j = 0; j < 2; j++) wmma::fill_fragment(acc[i][j], 0.f);

#pragma unroll
    for (int kc = 0; kc < 2; kc++) {
        if (F32IN) {
            const float* A = (const float*)Ain;
#pragma unroll
            for (int it = 0; it < 8; it++) {
                int slot = tid + it * 256;
                int r = slot >> 4, c4 = slot & 15;
                float4 v = make_float4(0.f, 0.f, 0.f, 0.f);
                if (row0 + r < n)
                    v = *(const float4*)(A + (size_t)(row0 + r) * 128 + kc * 64 + c4 * 4);
                __half2* dst = (__half2*)&As[r][c4 * 4];
                dst[0] = __floats2half2_rn(v.x, v.y);
                dst[1] = __floats2half2_rn(v.z, v.w);
            }
        } else {
            const __half* A = (const __half*)Ain;
#pragma unroll
            for (int it = 0; it < 4; it++) {
                int slot = tid + it * 256;
                int r = slot >> 3, c8 = slot & 7;
                int4 v = make_int4(0, 0, 0, 0);
                if (row0 + r < n)
                    v = *(const int4*)(A + (size_t)(row0 + r) * 128 + kc * 64 + c8 * 8);
                *(int4*)&As[r][c8 * 8] = v;
            }
        }
#pragma unroll
        for (int it = 0; it < 4; it++) {
            int slot = tid + it * 256;
            int r = slot >> 4, c8 = slot & 15;
            *(int4*)&Ws[r][c8 * 8] =
                *(const int4*)(W + (size_t)(kc * 64 + r) * 128 + c8 * 8);
        }
        __syncthreads();

#pragma unroll
        for (int k = 0; k < 4; k++) {
            wmma::fragment<wmma::matrix_b, 16, 16, 16, __half, wmma::row_major> b0, b1;
            wmma::load_matrix_sync(b0, &Ws[k * 16][wn * 32], 136);
            wmma::load_matrix_sync(b1, &Ws[k * 16][wn * 32 + 16], 136);
#pragma unroll
            for (int i = 0; i < 4; i++) {
                wmma::fragment<wmma::matrix_a, 16, 16, 16, __half, wmma::row_major> a;
                wmma::load_matrix_sync(a, &As[wm * 64 + i * 16][k * 16], 72);
                wmma::mma_sync(acc[i][0], a, b0, acc[i][0]);
                wmma::mma_sync(acc[i][1], a, b1, acc[i][1]);
            }
        }
        __syncthreads();
    }

    const int er = lane >> 3, ec = lane & 7;
#pragma unroll
    for (int i = 0; i < 4; i++)
#pragma unroll
        for (int j = 0; j < 2; j++) {
            wmma::store_matrix_sync(&cs[w][0][0], acc[i][j], 20, wmma::mem_row_major);
            __syncwarp();
#pragma unroll
            for (int t = 0; t < 4; t++) {
                int rr = er + t * 4;
                int gr = row0 + wm * 64 + i * 16 + rr;
                if (gr < n)
                    C[(size_t)gr * 64 + wn * 16 + j * 8 + ec] =
                        __floats2half2_rn(cs[w][rr][ec * 2], cs[w][rr][ec * 2 + 1]);
            }
            __syncwarp();
        }
}

// C[n,48](half) = A[n,128](half) @ W2h[128,48]. BM=128, 8 warps x 16 rows.
__global__ __launch_bounds__(256) void gemm40_smem(const __half* __restrict__ A,
                                                   __half2* __restrict__ C, int n) {
    __shared__ __half As[128][72];
    __shared__ __half Ws[64][56];
    __shared__ float  cs[8][16][20];

    const int tid = threadIdx.x;
    const int w = tid >> 5, lane = tid & 31;
    const int row0 = blockIdx.x * 128;

    wmma::fragment<wmma::accumulator, 16, 16, 16, float> acc[3];
#pragma unroll
    for (int j = 0; j < 3; j++) wmma::fill_fragment(acc[j], 0.f);

#pragma unroll
    for (int kc = 0; kc < 2; kc++) {
#pragma unroll
        for (int it = 0; it < 4; it++) {
            int slot = tid + it * 256;
            int r = slot >> 3, c8 = slot & 7;
            int4 v = make_int4(0, 0, 0, 0);
            if (row0 + r < n)
                v = *(const int4*)(A + (size_t)(row0 + r) * 128 + kc * 64 + c8 * 8);
            *(int4*)&As[r][c8 * 8] = v;
        }
        {
            int slot = tid;
#pragma unroll
            for (int it = 0; it < 2; it++, slot += 256) {
                if (slot < 384) {
                    int r = slot / 6, c8 = slot % 6;
                    *(int4*)&Ws[r][c8 * 8] =
                        *(const int4*)(g_w2h + (size_t)(kc * 64 + r) * 48 + c8 * 8);
                }
            }
        }
        __syncthreads();

#pragma unroll
        for (int k = 0; k < 4; k++) {
            wmma::fragment<wmma::matrix_a, 16, 16, 16, __half, wmma::row_major> a;
            wmma::load_matrix_sync(a, &As[w * 16][k * 16], 72);
#pragma unroll
            for (int j = 0; j < 3; j++) {
                wmma::fragment<wmma::matrix_b, 16, 16, 16, __half, wmma::row_major> b;
                wmma::load_matrix_sync(b, &Ws[k * 16][j * 16], 56);
                wmma::mma_sync(acc[j], a, b, acc[j]);
            }
        }
        __syncthreads();
    }

    const int er = lane >> 3, ec = lane & 7;
#pragma unroll
    for (int j = 0; j < 3; j++) {
        wmma::store_matrix_sync(&cs[w][0][0], acc[j], 20, wmma::mem_row_major);
        __syncwarp();
#pragma unroll
        for (int t = 0; t < 4; t++) {
            int rr = er + t * 4;
            int gr = row0 + w * 16 + rr;
            if (gr < n)
                C[(size_t)gr * 24 + j * 8 + ec] =
                    __floats2half2_rn(cs[w][rr][ec * 2], cs[w][rr][ec * 2 + 1]);
        }
        __syncwarp();
    }
}

// ---------------- aggregation (one warp per destination node) ----------------

__global__ void aggregate128_kernel(const __half* __restrict__ tmp,
                                    const float* __restrict__ bias,
                                    __half* __restrict__ out, int base, int count) {
    int wi = (blockIdx.x * blockDim.x + threadIdx.x) >> 5;
    int lane = threadIdx.x & 31;
    if (wi >= count) return;
    int w = base + wi;
    int beg = g_rowptr[w], end = g_rowptr[w + 1];
    const int g = lane >> 4, fl = lane & 15;

    float acc[8] = {0.f, 0.f, 0.f, 0.f, 0.f, 0.f, 0.f, 0.f};
    for (int e = beg + g; e < end; e += 2) {
        CN cn = g_cn[e];
        float4 v = *(const float4*)(tmp + (size_t)cn.c * 128 + fl * 8);
        const __half2* h = (const __half2*)&v;
#pragma unroll
        for (int j = 0; j < 4; j++) {
            float2 f = __half22float2(h[j]);
            acc[2 * j]     = fmaf(cn.nw, f.x, acc[2 * j]);
            acc[2 * j + 1] = fmaf(cn.nw, f.y, acc[2 * j + 1]);
        }
    }
#pragma unroll
    for (int k = 0; k < 8; k++) acc[k] += __shfl_xor_sync(0xffffffffu, acc[k], 16);

    if (g == 0) {
        __half2 hv[4];
#pragma unroll
        for (int j = 0; j < 4; j++) {
            float a0 = fmaxf(acc[2 * j]     + bias[fl * 8 + 2 * j],     0.f);
            float a1 = fmaxf(acc[2 * j + 1] + bias[fl * 8 + 2 * j + 1], 0.f);
            hv[j] = __floats2half2_rn(a0, a1);
        }
        *(int4*)(out + (size_t)w * 128 + fl * 8) = *(const int4*)hv;
    }
}

__global__ void aggregate40_kernel(const __half2* __restrict__ tmp,
                                   const float* __restrict__ bias,
                                   float* __restrict__ out, int n) {
    int w = (blockIdx.x * blockDim.x + threadIdx.x) >> 5;
    int lane = threadIdx.x & 31;
    if (w >= n) return;
    int beg = g_rowptr[w], end = g_rowptr[w + 1];

    float2 acc = make_float2(0.f, 0.f);
    if (lane < 24) {
        int e = beg;
        for (; e + 1 < end; e += 2) {
            CN c0 = g_cn[e], c1 = g_cn[e + 1];
            float2 f0 = __half22float2(tmp[(size_t)c0.c * 24 + lane]);
            float2 f1 = __half22float2(tmp[(size_t)c1.c * 24 + lane]);
            acc.x = fmaf(c0.nw, f0.x, acc.x); acc.x = fmaf(c1.nw, f1.x, acc.x);
            acc.y = fmaf(c0.nw, f0.y, acc.y); acc.y = fmaf(c1.nw, f1.y, acc.y);
        }
        if (e < end) {
            CN cn = g_cn[e];
            float2 f = __half22float2(tmp[(size_t)cn.c * 24 + lane]);
            acc.x = fmaf(cn.nw, f.x, acc.x);
            acc.y = fmaf(cn.nw, f.y, acc.y);
        }
    }
    if (lane < 20) {
        out[(size_t)w * 40 + 2 * lane]     = acc.x + bias[2 * lane];
        out[(size_t)w * 40 + 2 * lane + 1] = acc.y + bias[2 * lane + 1];
    }
}

// ---------------- launch -----------------------------------------------------

extern "C" void kernel_launch(void* const* d_in, const int* in_sizes, int n_in,
                              void* d_out, int out_size) {
    const float* x  = (const float*)d_in[0];
    const int*   ei = (const int*)d_in[1];
    const float* W0 = (const float*)d_in[2];
    const float* b0 = (const float*)d_in[3];
    const float* W1 = (const float*)d_in[4];
    const float* b1 = (const float*)d_in[5];
    const float* W2 = (const float*)d_in[6];
    const float* b2 = (const float*)d_in[7];
    float* out = (float*)d_out;

    const int n = in_sizes[0] / 128;
    const int e = in_sizes[1] / 2;

    __half *bufA, *bufB, *bufC, *w0h, *w1h;
    cudaGetSymbolAddress((void**)&bufA, g_bufA);
    cudaGetSymbolAddress((void**)&bufB, g_bufB);
    cudaGetSymbolAddress((void**)&bufC, g_bufC);
    cudaGetSymbolAddress((void**)&w0h, g_w0h);
    cudaGetSymbolAddress((void**)&w1h, g_w1h);

    static cudaStream_t s_side = nullptr;
    static cudaEvent_t ev_fork, ev_join, evA, evB, evC, evD;
    if (!s_side) {
        cudaStreamCreateWithFlags(&s_side, cudaStreamNonBlocking);
        cudaEventCreateWithFlags(&ev_fork, cudaEventDisableTiming);
        cudaEventCreateWithFlags(&ev_join, cudaEventDisableTiming);
        cudaEventCreateWithFlags(&evA, cudaEventDisableTiming);
        cudaEventCreateWithFlags(&evB, cudaEventDisableTiming);
        cudaEventCreateWithFlags(&evC, cudaEventDisableTiming);
        cudaEventCreateWithFlags(&evD, cudaEventDisableTiming);
    }

    const int nb = (n + 1023) / 1024;
    const int nh = ((n / 2 + 127) / 128) * 128;   // H0 rows (multiple of 128)
    const int n1 = n - nh;                        // H1 rows
    const int gb  = (n + 127) / 128;
    const int gb0 = nh / 128;
    const int gb1 = (n1 + 127) / 128;
    const int ab0 = (nh + 7) / 8;
    const int ab1 = (n1 + 7) / 8;
    const int ab  = (n + 7) / 8;

    // Fork: W conversion + layer-0 GEMM (reads x fp32 directly).
    cudaEventRecord(ev_fork, 0);
    cudaStreamWaitEvent(s_side, ev_fork, 0);
    convert_w_kernel<<<(32768 + 128 * 48 + 255) / 256, 256, 0, s_side>>>(W0, W1, W2);
    gemm128_smem<true><<<gb, 256, 0, s_side>>>(x, w0h, (__half2*)bufA, n);
    cudaEventRecord(ev_join, s_side);

    // Preprocessing on main stream (overlapped with gemm0). g_deg starts zero
    // (static init / restored by fill's atomicSub every run).
    degree_kernel<<<(e + 255) / 256, 256>>>(ei, e);
    scan1_kernel<<<nb, 1024>>>(n);
    scan2_kernel<<<1, 128>>>(nb);
    scan3_kernel<<<(n + 255) / 256, 256>>>(n);
    fill_kernel<<<(e + n + 255) / 256, 256>>>(ei, e, n);

    cudaStreamWaitEvent(0, ev_join, 0);

    // Layer 1: agg0 A->B, gemm1 B->C (half-split pipelined).
    aggregate128_kernel<<<ab0, 256>>>(bufA, b0, bufB, 0, nh);
    cudaEventRecord(evA, 0);
    cudaStreamWaitEvent(s_side, evA, 0);
    gemm128_smem<false><<<gb0, 256, 0, s_side>>>(bufB, w1h, (__half2*)bufC, nh);
    cudaEventRecord(evB, s_side);
    aggregate128_kernel<<<ab1, 256>>>(bufA, b0, bufB, nh, n1);
    gemm128_smem<false><<<gb1, 256>>>(bufB + (size_t)nh * 128, w1h,
                                      (__half2*)bufC + (size_t)nh * 64, n1);
    cudaStreamWaitEvent(0, evB, 0);

    // Layer 2: agg1 C->A, gemm40 A->B (half-split pipelined).
    aggregate128_kernel<<<ab0, 256>>>(bufC, b1, bufA, 0, nh);
    cudaEventRecord(evC, 0);
    cudaStreamWaitEvent(s_side, evC, 0);
    gemm40_smem<<<gb0, 256, 0, s_side>>>(bufA, (__half2*)bufB, nh);
    cudaEventRecord(evD, s_side);
    aggregate128_kernel<<<ab1, 256>>>(bufC, b1, bufA, nh, n1);
    gemm40_smem<<<gb1, 256>>>(bufA + (size_t)nh * 128,
                              (__half2*)bufB + (size_t)nh * 24, n1);
    cudaStreamWaitEvent(0, evD, 0);

    // Final aggregation -> fp32 logits.
    aggregate40_kernel<<<ab, 256>>>((const __half2*)bufB, b2, out, n);
}